// round 5
// baseline (speedup 1.0000x reference)
#include <cuda_runtime.h>

#define PATCH 32
#define MAXP  65536
#define NREAL 3

// Scratch (no allocations allowed)
__device__ float g_w[MAXP * 2];      // top-2 softmax scores per patch
__device__ int   g_meta[MAXP];       // i0 | i1<<8 | lvl<<16
__device__ int   g_start[MAXP];      // exclusive scan of counts
__device__ int   g_bsum[8192];       // per-8-patch (gate block) count sums

// ---------------------------------------------------------------------------
// Kernel 1: gate, ONE WARP per patch (original round-1 reduction order ->
// bit-identical logits -> identical routing). 8 patches / 256-thread block,
// 8192 blocks -> plenty of parallelism. Fused per-block count sum.
// ---------------------------------------------------------------------------
__global__ void gate_kernel(const float* __restrict__ x,
                            const float* __restrict__ Wg, int P) {
    __shared__ int wsum[8];
    int t = threadIdx.x;
    int wp = t >> 5, lane = t & 31;
    int gw = blockIdx.x * 8 + wp;

    float xv = x[(long)gw * PATCH + lane];
    float d0 = xv * Wg[0 * PATCH + lane];
    float d1 = xv * Wg[1 * PATCH + lane];
    float d2 = xv * Wg[2 * PATCH + lane];
    float d3 = xv * Wg[3 * PATCH + lane];
#pragma unroll
    for (int off = 16; off; off >>= 1) {
        d0 += __shfl_xor_sync(0xffffffffu, d0, off);
        d1 += __shfl_xor_sync(0xffffffffu, d1, off);
        d2 += __shfl_xor_sync(0xffffffffu, d2, off);
        d3 += __shfl_xor_sync(0xffffffffu, d3, off);
    }
    if (lane == 0) {
        float l[4] = {d0, d1, d2, d3};
        float m = fmaxf(fmaxf(l[0], l[1]), fmaxf(l[2], l[3]));
        float e[4], s = 0.f;
#pragma unroll
        for (int i = 0; i < 4; i++) { e[i] = expf(l[i] - m); s += e[i]; }
        float inv = 1.f / s;
        float sc[4];
#pragma unroll
        for (int i = 0; i < 4; i++) sc[i] = e[i] * inv;
        int i0 = 0;
#pragma unroll
        for (int i = 1; i < 4; i++) if (sc[i] > sc[i0]) i0 = i;
        int i1 = -1;
#pragma unroll
        for (int i = 0; i < 4; i++)
            if (i != i0 && (i1 < 0 || sc[i] > sc[i1])) i1 = i;
        int lv = -1;
        if (i0 < NREAL) lv = max(lv, i0);
        if (i1 < NREAL) lv = max(lv, i1);
        int lvl = max(lv, 0);
        g_w[gw * 2 + 0] = sc[i0];
        g_w[gw * 2 + 1] = sc[i1];
        g_meta[gw] = i0 | (i1 << 8) | (lvl << 16);
        wsum[wp] = 1 << lvl;
    }
    __syncthreads();
    if (t == 0) {
        int sum = 0;
#pragma unroll
        for (int i = 0; i < 8; i++) sum += wsum[i];
        g_bsum[blockIdx.x] = sum;
    }
}

// ---------------------------------------------------------------------------
// Kernel 2: per-patch starts. Block offset = sum of preceding 32 gate-block
// sums per starts-block (strided redundant reduce over <=8160 ints from L2),
// then intra-block shfl scan over 256 patches.
// ---------------------------------------------------------------------------
__global__ void starts_kernel(int P) {
    __shared__ int ws[8];
    __shared__ int bofs;
    int t = threadIdx.x, lane = t & 31, wp = t >> 5;
    int p = blockIdx.x * 256 + t;

    int lim = blockIdx.x * 32;          // preceding g_bsum entries
    int bo = 0;
    for (int i = t; i < lim; i += 256) bo += g_bsum[i];
    bo = __reduce_add_sync(0xffffffffu, bo);
    if (lane == 0) ws[wp] = bo;
    __syncthreads();
    if (t == 0) {
        int s = 0;
#pragma unroll
        for (int i = 0; i < 8; i++) s += ws[i];
        bofs = s;
    }
    __syncthreads();

    int cnt = (p < P) ? (1 << ((g_meta[p] >> 16) & 3)) : 0;
    int inc = cnt;
#pragma unroll
    for (int o = 1; o < 32; o <<= 1) {
        int u = __shfl_up_sync(0xffffffffu, inc, o);
        if (lane >= o) inc += u;
    }
    __syncthreads();
    if (lane == 31) ws[wp] = inc;
    __syncthreads();
    if (wp == 0) {
        int s = (lane < 8) ? ws[lane] : 0;
#pragma unroll
        for (int o = 1; o < 8; o <<= 1) {
            int u = __shfl_up_sync(0xffffffffu, s, o);
            if (lane >= o) s += u;
        }
        if (lane < 8) ws[lane] = s;
    }
    __syncthreads();
    int off = wp ? ws[wp - 1] : 0;
    if (p < P) g_start[p] = bofs + off + inc - cnt;
}

// ---------------------------------------------------------------------------
// Kernel 3: hybrid writer, ONE WARP per patch.
//  - new_x / new_mask: float4 vector stores (these sections are ALWAYS 16B
//    aligned: base offsets start*32 and T*32+start*32 floats). Lane mapping
//    c = lane>>3 (child), q = lane&7 (quad); gather quads straight from L1.
//  - x_final: lvl-specialized coalesced scalar stores (no alignment assumed).
// Output layout (floats):
//   [0,32T) new_x   [32T,64T) new_mask  [64T,65T) new_size
//   [65T,67T) weights  [67T,69T) expert_idx  [69T,165T) x_final [T,3,32]
// ---------------------------------------------------------------------------
__global__ void write_kernel(const float* __restrict__ x,
                             const float* __restrict__ mask,
                             float* __restrict__ out, int P, unsigned T) {
    unsigned w = (blockIdx.x * blockDim.x + threadIdx.x) >> 5;
    unsigned lane = threadIdx.x & 31;
    if (w >= (unsigned)P) return;

    int meta = g_meta[w];
    unsigned start = (unsigned)g_start[w];
    int i0 = meta & 255, i1 = (meta >> 8) & 255, lvl = (meta >> 16) & 3;
    int cnt = 1 << lvl, sz = 32 >> lvl;

    // ---- vector part: new_x / new_mask ----
    {
        const float4* xp = (const float4*)x + (long)w * 8;
        const float4* mp = (const float4*)mask + (long)w * 8;
        int c = lane >> 3, q = lane & 7;
        bool qv = (q * 4) < sz;                 // whole-quad validity
        int gi = qv ? ((c * sz) >> 2) + q : 0;
        float4 gx = xp[gi];                     // L1 broadcast hits
        float4 gm = mp[gi];
        if (!qv) { gx = make_float4(0.f,0.f,0.f,0.f);
                   gm = make_float4(0.f,0.f,0.f,0.f); }
        if (c < cnt) {
            float4* out4 = (float4*)out;
            long idx4 = (long)(start + c) * 8 + q;
            out4[idx4]          = gx;
            out4[(long)T * 8 + idx4] = gm;
        }
    }

    // ---- scalar part: x_final + small fields ----
    float xv = x[w * 32u + lane];
    float mv = mask[w * 32u + lane];
    float pm = xv * mv;

    float* pf = out + T * 69u + start * 96u + lane;
    float* ps = out + T * 64u + start;
    float* pw = out + T * 65u + start * 2u + lane;
    float* pe = out + T * 67u + start * 2u + lane;

    switch (lvl) {
    case 0: {   // cnt=1, sz=32
        pf[0] = pm;  pf[32] = 0.f;  pf[64] = 0.f;
        if (lane == 0) ps[0] = 32.f;
        if (lane < 2) {
            pw[0] = (lane & 1) ? g_w[w * 2 + 1] : g_w[w * 2];
            pe[0] = (float)((lane & 1) ? i1 : i0);
        }
        break;
    }
    case 1: {   // cnt=2, sz=16
        bool lo = lane < 16, hi = !lo;
        pf[0]  = pm;  pf[32]  = lo ? pm : 0.f;  pf[64]  = 0.f;
        pf[96] = pm;  pf[128] = hi ? pm : 0.f;  pf[160] = 0.f;
        if (lane < 2) ps[lane] = 16.f;
        if (lane < 4) {
            pw[0] = (lane & 1) ? g_w[w * 2 + 1] : g_w[w * 2];
            pe[0] = (float)((lane & 1) ? i1 : i0);
        }
        break;
    }
    default: {  // lvl=2: cnt=4, sz=8
        bool h0 = lane < 16, h1 = !h0;
        bool o0 = lane < 8, o1 = (lane >= 8) & h0;
        bool o2 = (lane >= 16) & (lane < 24), o3 = lane >= 24;
        pf[0]   = 0.f;  pf[32]  = h0 ? pm : 0.f;  pf[64]  = o0 ? pm : 0.f;
        pf[96]  = 0.f;  pf[128] = h0 ? pm : 0.f;  pf[160] = o1 ? pm : 0.f;
        pf[192] = 0.f;  pf[224] = h1 ? pm : 0.f;  pf[256] = o2 ? pm : 0.f;
        pf[288] = 0.f;  pf[320] = h1 ? pm : 0.f;  pf[352] = o3 ? pm : 0.f;
        if (lane < 4) ps[lane] = 8.f;
        if (lane < 8) {
            pw[0] = (lane & 1) ? g_w[w * 2 + 1] : g_w[w * 2];
            pe[0] = (float)((lane & 1) ? i1 : i0);
        }
        break;
    }
    }
}

// ---------------------------------------------------------------------------
extern "C" void kernel_launch(void* const* d_in, const int* in_sizes, int n_in,
                              void* d_out, int out_size) {
    const float* x    = (const float*)d_in[0];
    const float* mask = (const float*)d_in[1];
    const float* Wg   = (const float*)d_in[2];
    float* out = (float*)d_out;

    int n = in_sizes[0];
    int P = n / PATCH;                 // 65536
    unsigned T = (unsigned)(out_size / 165);

    gate_kernel<<<P / 8, 256>>>(x, Wg, P);       // 8192 blocks
    starts_kernel<<<(P + 255) / 256, 256>>>(P);  // 256 blocks
    write_kernel<<<(P * 32 + 255) / 256, 256>>>(x, mask, out, P, T);
}

// round 6
// speedup vs baseline: 1.2094x; 1.2094x over previous
#include <cuda_runtime.h>

#define PATCH 32
#define MAXP  65536
#define NREAL 3

// Scratch (no allocations allowed)
__device__ float g_w[MAXP * 2];      // top-2 softmax scores per patch
__device__ int   g_meta[MAXP];       // i0 | i1<<8 | lvl<<16
__device__ int   g_start[MAXP];      // exclusive scan of counts
__device__ int   g_bsum[1024];       // per-64-patch block count sums

// ---------------------------------------------------------------------------
// Kernel 1: gate. 4 threads per patch, ONE EXPERT per thread. Full in-thread
// butterfly tree (same summation order as the round-2/3 gate that passed),
// then 4 shfls to allgather the 4 logits within the quad. 64 patches per
// 256-thread block -> 1024 blocks, 8192 warps, high ILP, almost no shfl.
// ---------------------------------------------------------------------------
__global__ void gate_kernel(const float4* __restrict__ x4,
                            const float4* __restrict__ Wg4, int P) {
    __shared__ float4 wg4[32];       // 4 experts x 8 quads
    __shared__ int wsum[8];
    int t = threadIdx.x;
    if (t < 32) wg4[t] = Wg4[t];
    __syncthreads();

    int p  = blockIdx.x * 64 + (t >> 2);
    int e  = t & 3;                  // expert owned by this thread
    int pc = p < P ? p : P - 1;      // clamp (keep warp convergent)

    float a[32];
#pragma unroll
    for (int q = 0; q < 8; q++) {
        float4 v = x4[(unsigned)pc * 8u + q];    // quad-broadcast L1 hit
        float4 wv = wg4[e * 8 + q];
        a[q * 4 + 0] = v.x * wv.x;
        a[q * 4 + 1] = v.y * wv.y;
        a[q * 4 + 2] = v.z * wv.z;
        a[q * 4 + 3] = v.w * wv.w;
    }
#pragma unroll
    for (int off = 16; off >= 1; off >>= 1)
#pragma unroll
        for (int i = 0; i < off; i++) a[i] += a[i + off];
    float lgt = a[0];

    // allgather 4 logits within the quad
    int lane = t & 31;
    int qb = lane & ~3;
    float l0 = __shfl_sync(0xffffffffu, lgt, qb + 0);
    float l1 = __shfl_sync(0xffffffffu, lgt, qb + 1);
    float l2 = __shfl_sync(0xffffffffu, lgt, qb + 2);
    float l3 = __shfl_sync(0xffffffffu, lgt, qb + 3);

    int lvl = 0;
    if (e == 0 && p < P) {
        float l[4] = {l0, l1, l2, l3};
        float m = fmaxf(fmaxf(l[0], l[1]), fmaxf(l[2], l[3]));
        float ex[4], s = 0.f;
#pragma unroll
        for (int i = 0; i < 4; i++) { ex[i] = expf(l[i] - m); s += ex[i]; }
        float inv = 1.f / s;
        float sc[4];
#pragma unroll
        for (int i = 0; i < 4; i++) sc[i] = ex[i] * inv;
        int i0 = 0;
#pragma unroll
        for (int i = 1; i < 4; i++) if (sc[i] > sc[i0]) i0 = i;
        int i1 = -1;
#pragma unroll
        for (int i = 0; i < 4; i++)
            if (i != i0 && (i1 < 0 || sc[i] > sc[i1])) i1 = i;
        int lv = -1;
        if (i0 < NREAL) lv = max(lv, i0);
        if (i1 < NREAL) lv = max(lv, i1);
        lvl = max(lv, 0);
        g_w[p * 2 + 0] = sc[i0];
        g_w[p * 2 + 1] = sc[i1];
        g_meta[p] = i0 | (i1 << 8) | (lvl << 16);
    }
    int cnt = (e == 0 && p < P) ? (1 << lvl) : 0;
    int ws = __reduce_add_sync(0xffffffffu, cnt);
    if (lane == 0) wsum[t >> 5] = ws;
    __syncthreads();
    if (t == 0) {
        int sum = 0;
#pragma unroll
        for (int i = 0; i < 8; i++) sum += wsum[i];
        g_bsum[blockIdx.x] = sum;
    }
}

// ---------------------------------------------------------------------------
// Kernel 2: per-patch starts. Block offset = redundant reduce of preceding
// 64-patch sums (4 per starts-block), then intra-block shfl scan.
// ---------------------------------------------------------------------------
__global__ void starts_kernel(int P) {
    __shared__ int ws[8];
    __shared__ int bofs;
    int t = threadIdx.x, lane = t & 31, wp = t >> 5;
    int p = blockIdx.x * 256 + t;

    int lim = blockIdx.x * 4;
    int bo = (t < lim) ? g_bsum[t] : 0;   // lim <= 1020 < 256? no: lim up to 1020
    for (int i = t + 256; i < lim; i += 256) bo += g_bsum[i];
    bo = __reduce_add_sync(0xffffffffu, bo);
    if (lane == 0) ws[wp] = bo;
    __syncthreads();
    if (t == 0) {
        int s = 0;
#pragma unroll
        for (int i = 0; i < 8; i++) s += ws[i];
        bofs = s;
    }
    __syncthreads();

    int cnt = (p < P) ? (1 << ((g_meta[p] >> 16) & 3)) : 0;
    int inc = cnt;
#pragma unroll
    for (int o = 1; o < 32; o <<= 1) {
        int u = __shfl_up_sync(0xffffffffu, inc, o);
        if (lane >= o) inc += u;
    }
    __syncthreads();
    if (lane == 31) ws[wp] = inc;
    __syncthreads();
    if (wp == 0) {
        int s = (lane < 8) ? ws[lane] : 0;
#pragma unroll
        for (int o = 1; o < 8; o <<= 1) {
            int u = __shfl_up_sync(0xffffffffu, s, o);
            if (lane >= o) s += u;
        }
        if (lane < 8) ws[lane] = s;
    }
    __syncthreads();
    int off = wp ? ws[wp - 1] : 0;
    if (p < P) g_start[p] = bofs + off + inc - cnt;
}

// ---------------------------------------------------------------------------
// Kernel 3: writer, ONE WARP per patch. new_x/new_mask always via STG.128.
// x_final: if T is even (8B-aligned section base) use float2 stores where
// lane L owns value-pair (L&15) and wave k stores rows {2k, 2k+1}; else the
// proven coalesced-scalar switch. Output layout (floats):
//   [0,32T) new_x   [32T,64T) new_mask  [64T,65T) new_size
//   [65T,67T) weights  [67T,69T) expert_idx  [69T,165T) x_final [T,3,32]
// ---------------------------------------------------------------------------
template <bool EVEN>
__global__ void write_kernel(const float* __restrict__ x,
                             const float* __restrict__ mask,
                             float* __restrict__ out, int P, unsigned T) {
    unsigned w = (blockIdx.x * blockDim.x + threadIdx.x) >> 5;
    unsigned lane = threadIdx.x & 31;
    if (w >= (unsigned)P) return;

    int meta = g_meta[w];
    unsigned start = (unsigned)g_start[w];
    int i0 = meta & 255, i1 = (meta >> 8) & 255, lvl = (meta >> 16) & 3;
    int cnt = 1 << lvl, sz = 32 >> lvl;

    // ---- new_x / new_mask: always 16B-aligned vector stores ----
    {
        const float4* xp = (const float4*)x + (unsigned)w * 8u;
        const float4* mp = (const float4*)mask + (unsigned)w * 8u;
        int c = lane >> 3, q = lane & 7;
        bool qv = (q * 4) < sz;
        int gi = qv ? ((c * sz) >> 2) + q : 0;
        float4 gx = xp[gi];
        float4 gm = mp[gi];
        if (!qv) { gx = make_float4(0.f,0.f,0.f,0.f);
                   gm = make_float4(0.f,0.f,0.f,0.f); }
        if (c < cnt) {
            float4* out4 = (float4*)out;
            unsigned idx4 = (start + c) * 8u + q;
            out4[idx4] = gx;
            out4[T * 8u + idx4] = gm;
        }
    }

    // ---- small fields ----
    float* ps = out + T * 64u + start;
    float* pw = out + T * 65u + start * 2u + lane;
    float* pe = out + T * 67u + start * 2u + lane;
    if (lane < (unsigned)cnt) ps[lane] = (float)sz;
    if (lane < (unsigned)(cnt * 2)) {
        pw[0] = (lane & 1) ? g_w[w * 2 + 1] : g_w[w * 2];
        pe[0] = (float)((lane & 1) ? i1 : i0);
    }

    // ---- x_final ----
    if (EVEN) {
        // lane owns pair q16 = lane&15 of each 32-float row
        unsigned q16 = lane & 15u, h = lane >> 4;
        float2 xw = ((const float2*)x)[w * 16u + q16];
        float2 mw = ((const float2*)mask)[w * 16u + q16];
        float2 pm2 = make_float2(xw.x * mw.x, xw.y * mw.y);
        const float2 z2 = make_float2(0.f, 0.f);
        int rows = 3 * cnt;
        int j0 = (int)(q16 * 2u);
        unsigned b2 = (T >> 1) * 69u + start * 48u + q16;   // float2 units
        int lo_par = 0, hi_par = 0;
#pragma unroll
        for (int rb = 0; rb < 12; rb += 2) {
            if (rb >= rows) break;
            int row = rb + (int)h;
            int c = (row * 11) >> 5;       // row/3 for row<12
            int l = row - 3 * c;
            bool on = false;
            if (l == lvl) {
                int lo = c * sz; on = (j0 >= lo) & (j0 < lo + sz);
            } else if (lvl >= 1 && l == lvl - 1) {
                lo_par = (c >> 1) * (sz * 2);
                on = (j0 >= lo_par) & (j0 < lo_par + sz * 2);
            }
            float2 v = on ? pm2 : z2;
            if (row < rows) ((float2*)out)[b2 + (unsigned)row * 16u] = v;
        }
    } else {
        float xv = x[w * 32u + lane];
        float mv = mask[w * 32u + lane];
        float pm = xv * mv;
        float* pf = out + T * 69u + start * 96u + lane;
        switch (lvl) {
        case 0:
            pf[0] = pm;  pf[32] = 0.f;  pf[64] = 0.f;
            break;
        case 1: {
            bool lo = lane < 16, hi = !lo;
            pf[0]  = pm;  pf[32]  = lo ? pm : 0.f;  pf[64]  = 0.f;
            pf[96] = pm;  pf[128] = hi ? pm : 0.f;  pf[160] = 0.f;
            break;
        }
        default: {
            bool h0 = lane < 16, h1 = !h0;
            bool o0 = lane < 8, o1 = (lane >= 8) & h0;
            bool o2 = (lane >= 16) & (lane < 24), o3 = lane >= 24;
            pf[0]   = 0.f;  pf[32]  = h0 ? pm : 0.f;  pf[64]  = o0 ? pm : 0.f;
            pf[96]  = 0.f;  pf[128] = h0 ? pm : 0.f;  pf[160] = o1 ? pm : 0.f;
            pf[192] = 0.f;  pf[224] = h1 ? pm : 0.f;  pf[256] = o2 ? pm : 0.f;
            pf[288] = 0.f;  pf[320] = h1 ? pm : 0.f;  pf[352] = o3 ? pm : 0.f;
            break;
        }
        }
    }
}

// ---------------------------------------------------------------------------
extern "C" void kernel_launch(void* const* d_in, const int* in_sizes, int n_in,
                              void* d_out, int out_size) {
    const float* x    = (const float*)d_in[0];
    const float* mask = (const float*)d_in[1];
    const float* Wg   = (const float*)d_in[2];
    float* out = (float*)d_out;

    int n = in_sizes[0];
    int P = n / PATCH;                 // 65536
    unsigned T = (unsigned)(out_size / 165);

    gate_kernel<<<(P + 63) / 64, 256>>>((const float4*)x, (const float4*)Wg, P);
    starts_kernel<<<(P + 255) / 256, 256>>>(P);
    int wb = (P * 32 + 255) / 256;
    if ((T & 1u) == 0)
        write_kernel<true><<<wb, 256>>>(x, mask, out, P, T);
    else
        write_kernel<false><<<wb, 256>>>(x, mask, out, P, T);
}

// round 8
// speedup vs baseline: 1.2214x; 1.0100x over previous
#include <cuda_runtime.h>

#define PATCH 32
#define MAXP  65536
#define NREAL 3

// Scratch (no allocations allowed)
__device__ float g_w[MAXP * 2];      // top-2 softmax scores per patch
__device__ int   g_meta[MAXP];       // i0 | i1<<8 | lvl<<16
__device__ int   g_start[MAXP];      // exclusive scan of counts
__device__ int   g_bsum[1024];       // per-64-patch block count sums

// ---------------------------------------------------------------------------
// Kernel 1: gate. 4 threads per patch, one expert per thread, but x is staged
// through padded smem: coalesced GLD (512 consecutive float4/block), rows
// padded to 36 floats (9 float4) -> STS.128 and LDS.128 both bank-conflict
// free. In-thread reduction tree identical in shape/order to the passing
// round-2/3/6 gate -> identical routing. 64 patches/block, 1024 blocks.
// ---------------------------------------------------------------------------
__global__ void gate_kernel(const float4* __restrict__ x4,
                            const float4* __restrict__ Wg4, int P) {
    __shared__ float4 wg4[32];           // 4 experts x 8 quads
    __shared__ float4 xs[64 * 9];        // 64 patches, padded rows (36 floats)
    __shared__ int wsum[8];
    int t = threadIdx.x;
    if (t < 32) wg4[t] = Wg4[t];

    // coalesced stage-in: 512 float4 per block
    unsigned base = (unsigned)blockIdx.x * 512u;
#pragma unroll
    for (int k = 0; k < 2; k++) {
        unsigned g = (unsigned)t + (unsigned)k * 256u;      // 0..511
        float4 v = x4[base + g];
        xs[(g >> 3) * 9u + (g & 7u)] = v;
    }
    __syncthreads();

    int p = blockIdx.x * 64 + (t >> 2);
    int e = t & 3;                       // expert owned by this thread
    int pr = t >> 2;                     // patch row in smem

    float a[32];
#pragma unroll
    for (int q = 0; q < 8; q++) {
        float4 v  = xs[pr * 9 + q];      // 4-way broadcast, conflict-free
        float4 wv = wg4[e * 8 + q];
        a[q * 4 + 0] = v.x * wv.x;
        a[q * 4 + 1] = v.y * wv.y;
        a[q * 4 + 2] = v.z * wv.z;
        a[q * 4 + 3] = v.w * wv.w;
    }
#pragma unroll
    for (int off = 16; off >= 1; off >>= 1)
#pragma unroll
        for (int i = 0; i < off; i++) a[i] += a[i + off];
    float lgt = a[0];

    // allgather the quad's 4 logits
    int lane = t & 31;
    int qb = lane & ~3;
    float l0 = __shfl_sync(0xffffffffu, lgt, qb + 0);
    float l1 = __shfl_sync(0xffffffffu, lgt, qb + 1);
    float l2 = __shfl_sync(0xffffffffu, lgt, qb + 2);
    float l3 = __shfl_sync(0xffffffffu, lgt, qb + 3);

    int lvl = 0;
    if (e == 0 && p < P) {
        float l[4] = {l0, l1, l2, l3};
        float m = fmaxf(fmaxf(l[0], l[1]), fmaxf(l[2], l[3]));
        float ex[4], s = 0.f;
#pragma unroll
        for (int i = 0; i < 4; i++) { ex[i] = expf(l[i] - m); s += ex[i]; }
        float inv = 1.f / s;
        float sc[4];
#pragma unroll
        for (int i = 0; i < 4; i++) sc[i] = ex[i] * inv;
        int i0 = 0;
#pragma unroll
        for (int i = 1; i < 4; i++) if (sc[i] > sc[i0]) i0 = i;
        int i1 = -1;
#pragma unroll
        for (int i = 0; i < 4; i++)
            if (i != i0 && (i1 < 0 || sc[i] > sc[i1])) i1 = i;
        int lv = -1;
        if (i0 < NREAL) lv = max(lv, i0);
        if (i1 < NREAL) lv = max(lv, i1);
        lvl = max(lv, 0);
        g_w[p * 2 + 0] = sc[i0];
        g_w[p * 2 + 1] = sc[i1];
        g_meta[p] = i0 | (i1 << 8) | (lvl << 16);
    }
    int cnt = (e == 0 && p < P) ? (1 << lvl) : 0;
    int ws = __reduce_add_sync(0xffffffffu, cnt);
    if (lane == 0) wsum[t >> 5] = ws;
    __syncthreads();
    if (t == 0) {
        int sum = 0;
#pragma unroll
        for (int i = 0; i < 8; i++) sum += wsum[i];
        g_bsum[blockIdx.x] = sum;
    }
}

// ---------------------------------------------------------------------------
// Kernel 2: per-patch starts. Block offset = redundant reduce of preceding
// 64-patch sums (4*bid entries from L2), then intra-block shfl scan.
// ---------------------------------------------------------------------------
__global__ void starts_kernel(int P) {
    __shared__ int ws[8];
    __shared__ int bofs;
    int t = threadIdx.x, lane = t & 31, wp = t >> 5;
    int p = blockIdx.x * 256 + t;

    int lim = blockIdx.x * 4;
    int bo = (t < lim) ? g_bsum[t] : 0;
    for (int i = t + 256; i < lim; i += 256) bo += g_bsum[i];
    bo = __reduce_add_sync(0xffffffffu, bo);
    if (lane == 0) ws[wp] = bo;
    __syncthreads();
    if (t == 0) {
        int s = 0;
#pragma unroll
        for (int i = 0; i < 8; i++) s += ws[i];
        bofs = s;
    }
    __syncthreads();

    int cnt = (p < P) ? (1 << ((g_meta[p] >> 16) & 3)) : 0;
    int inc = cnt;
#pragma unroll
    for (int o = 1; o < 32; o <<= 1) {
        int u = __shfl_up_sync(0xffffffffu, inc, o);
        if (lane >= o) inc += u;
    }
    __syncthreads();
    if (lane == 31) ws[wp] = inc;
    __syncthreads();
    if (wp == 0) {
        int s = (lane < 8) ? ws[lane] : 0;
#pragma unroll
        for (int o = 1; o < 8; o <<= 1) {
            int u = __shfl_up_sync(0xffffffffu, s, o);
            if (lane >= o) s += u;
        }
        if (lane < 8) ws[lane] = s;
    }
    __syncthreads();
    int off = wp ? ws[wp - 1] : 0;
    if (p < P) g_start[p] = bofs + off + inc - cnt;
}

// ---------------------------------------------------------------------------
// Kernel 3: writer, ONE WARP per patch. new_x/new_mask always via STG.128.
// x_final: if T is even (8B-aligned section base) use float2 stores where
// lane L owns value-pair (L&15) and wave k stores rows {2k, 2k+1}; else the
// proven coalesced-scalar switch. Output layout (floats):
//   [0,32T) new_x   [32T,64T) new_mask  [64T,65T) new_size
//   [65T,67T) weights  [67T,69T) expert_idx  [69T,165T) x_final [T,3,32]
// ---------------------------------------------------------------------------
template <bool EVEN>
__global__ void write_kernel(const float* __restrict__ x,
                             const float* __restrict__ mask,
                             float* __restrict__ out, int P, unsigned T) {
    unsigned w = (blockIdx.x * blockDim.x + threadIdx.x) >> 5;
    unsigned lane = threadIdx.x & 31;
    if (w >= (unsigned)P) return;

    int meta = g_meta[w];
    unsigned start = (unsigned)g_start[w];
    int i0 = meta & 255, i1 = (meta >> 8) & 255, lvl = (meta >> 16) & 3;
    int cnt = 1 << lvl, sz = 32 >> lvl;

    // ---- new_x / new_mask: always 16B-aligned vector stores ----
    {
        const float4* xp = (const float4*)x + (unsigned)w * 8u;
        const float4* mp = (const float4*)mask + (unsigned)w * 8u;
        int c = lane >> 3, q = lane & 7;
        bool qv = (q * 4) < sz;
        int gi = qv ? ((c * sz) >> 2) + q : 0;
        float4 gx = xp[gi];
        float4 gm = mp[gi];
        if (!qv) { gx = make_float4(0.f,0.f,0.f,0.f);
                   gm = make_float4(0.f,0.f,0.f,0.f); }
        if (c < cnt) {
            float4* out4 = (float4*)out;
            unsigned idx4 = (start + c) * 8u + q;
            out4[idx4] = gx;
            out4[T * 8u + idx4] = gm;
        }
    }

    // ---- small fields ----
    float* ps = out + T * 64u + start;
    float* pw = out + T * 65u + start * 2u + lane;
    float* pe = out + T * 67u + start * 2u + lane;
    if (lane < (unsigned)cnt) ps[lane] = (float)sz;
    if (lane < (unsigned)(cnt * 2)) {
        pw[0] = (lane & 1) ? g_w[w * 2 + 1] : g_w[w * 2];
        pe[0] = (float)((lane & 1) ? i1 : i0);
    }

    // ---- x_final ----
    if (EVEN) {
        unsigned q16 = lane & 15u, h = lane >> 4;
        float2 xw = ((const float2*)x)[w * 16u + q16];
        float2 mw = ((const float2*)mask)[w * 16u + q16];
        float2 pm2 = make_float2(xw.x * mw.x, xw.y * mw.y);
        const float2 z2 = make_float2(0.f, 0.f);
        int rows = 3 * cnt;
        int j0 = (int)(q16 * 2u);
        unsigned b2 = (T >> 1) * 69u + start * 48u + q16;   // float2 units
#pragma unroll
        for (int rb = 0; rb < 12; rb += 2) {
            if (rb >= rows) break;
            int row = rb + (int)h;
            int c = (row * 11) >> 5;       // row/3 for row<12
            int l = row - 3 * c;
            bool on = false;
            if (l == lvl) {
                int lo = c * sz; on = (j0 >= lo) & (j0 < lo + sz);
            } else if (lvl >= 1 && l == lvl - 1) {
                int lo = (c >> 1) * (sz * 2);
                on = (j0 >= lo) & (j0 < lo + sz * 2);
            }
            float2 v = on ? pm2 : z2;
            if (row < rows) ((float2*)out)[b2 + (unsigned)row * 16u] = v;
        }
    } else {
        float xv = x[w * 32u + lane];
        float mv = mask[w * 32u + lane];
        float pm = xv * mv;
        float* pf = out + T * 69u + start * 96u + lane;
        switch (lvl) {
        case 0:
            pf[0] = pm;  pf[32] = 0.f;  pf[64] = 0.f;
            break;
        case 1: {
            bool lo = lane < 16, hi = !lo;
            pf[0]  = pm;  pf[32]  = lo ? pm : 0.f;  pf[64]  = 0.f;
            pf[96] = pm;  pf[128] = hi ? pm : 0.f;  pf[160] = 0.f;
            break;
        }
        default: {
            bool h0 = lane < 16, h1 = !h0;
            bool o0 = lane < 8, o1 = (lane >= 8) & h0;
            bool o2 = (lane >= 16) & (lane < 24), o3 = lane >= 24;
            pf[0]   = 0.f;  pf[32]  = h0 ? pm : 0.f;  pf[64]  = o0 ? pm : 0.f;
            pf[96]  = 0.f;  pf[128] = h0 ? pm : 0.f;  pf[160] = o1 ? pm : 0.f;
            pf[192] = 0.f;  pf[224] = h1 ? pm : 0.f;  pf[256] = o2 ? pm : 0.f;
            pf[288] = 0.f;  pf[320] = h1 ? pm : 0.f;  pf[352] = o3 ? pm : 0.f;
            break;
        }
        }
    }
}

// ---------------------------------------------------------------------------
extern "C" void kernel_launch(void* const* d_in, const int* in_sizes, int n_in,
                              void* d_out, int out_size) {
    const float* x    = (const float*)d_in[0];
    const float* mask = (const float*)d_in[1];
    const float* Wg   = (const float*)d_in[2];
    float* out = (float*)d_out;

    int n = in_sizes[0];
    int P = n / PATCH;                 // 65536
    unsigned T = (unsigned)(out_size / 165);

    gate_kernel<<<(P + 63) / 64, 256>>>((const float4*)x, (const float4*)Wg, P);
    starts_kernel<<<(P + 255) / 256, 256>>>(P);
    int wb = (P * 32 + 255) / 256;
    if ((T & 1u) == 0)
        write_kernel<true><<<wb, 256>>>(x, mask, out, P, T);
    else
        write_kernel<false><<<wb, 256>>>(x, mask, out, P, T);
}

// round 9
// speedup vs baseline: 1.3294x; 1.0884x over previous
#include <cuda_runtime.h>

#define PATCH 32
#define MAXP  65536
#define NREAL 3

// Scratch (no allocations allowed)
__device__ float2 g_w2[MAXP];        // top-2 softmax scores per patch
__device__ int    g_meta[MAXP];      // i0 | i1<<8 | lvl<<16
__device__ int    g_start[MAXP];     // exclusive scan of counts
__device__ int    g_bsum[1024];      // per-64-patch block count sums

// ---------------------------------------------------------------------------
// Kernel 1: gate. 4 threads per patch; thread qt owns elements [8qt, 8qt+8)
// and computes partial dots for ALL 4 experts via FMA chains (2 coalesced
// float4 loads per thread; warp spans 4KB contiguous). Quad butterfly
// (xor 1, xor 2) completes all 4 logits in every quad thread; softmax/top-2
// computed redundantly (quad-uniform, no divergence). Fused per-block count
// sum. 64 patches / 256-thread block -> 1024 blocks, ~25 regs, high occ.
// ---------------------------------------------------------------------------
__global__ void gate_kernel(const float4* __restrict__ x4,
                            const float4* __restrict__ Wg4, int P) {
    __shared__ float4 wg4[32];           // 4 experts x 8 quads
    __shared__ int wsum[8];
    int t = threadIdx.x;
    int lane = t & 31;
    int qt = t & 3;
    if (t < 32) wg4[t] = Wg4[t];
    __syncthreads();

    int p = blockIdx.x * 64 + (t >> 2);

    float4 xa = x4[(unsigned)p * 8u + qt * 2];
    float4 xb = x4[(unsigned)p * 8u + qt * 2 + 1];

    float d[4];
#pragma unroll
    for (int e = 0; e < 4; e++) {
        float4 wa = wg4[e * 8 + qt * 2];
        float4 wb = wg4[e * 8 + qt * 2 + 1];
        float s = xa.x * wa.x;
        s = fmaf(xa.y, wa.y, s);
        s = fmaf(xa.z, wa.z, s);
        s = fmaf(xa.w, wa.w, s);
        s = fmaf(xb.x, wb.x, s);
        s = fmaf(xb.y, wb.y, s);
        s = fmaf(xb.z, wb.z, s);
        s = fmaf(xb.w, wb.w, s);
        d[e] = s;
    }
    // quad reduction: after these, every quad thread holds all 4 full logits
#pragma unroll
    for (int e = 0; e < 4; e++) {
        d[e] += __shfl_xor_sync(0xffffffffu, d[e], 1);
        d[e] += __shfl_xor_sync(0xffffffffu, d[e], 2);
    }

    // softmax + top-2 (computed by all quad threads, results quad-uniform)
    float m = fmaxf(fmaxf(d[0], d[1]), fmaxf(d[2], d[3]));
    float ex[4], s = 0.f;
#pragma unroll
    for (int i = 0; i < 4; i++) { ex[i] = expf(d[i] - m); s += ex[i]; }
    float inv = 1.f / s;
    float sc[4];
#pragma unroll
    for (int i = 0; i < 4; i++) sc[i] = ex[i] * inv;
    int i0 = 0;
#pragma unroll
    for (int i = 1; i < 4; i++) if (sc[i] > sc[i0]) i0 = i;
    int i1 = -1;
#pragma unroll
    for (int i = 0; i < 4; i++)
        if (i != i0 && (i1 < 0 || sc[i] > sc[i1])) i1 = i;
    int lv = -1;
    if (i0 < NREAL) lv = max(lv, i0);
    if (i1 < NREAL) lv = max(lv, i1);
    int lvl = max(lv, 0);

    if (qt == 0 && p < P) {
        g_w2[p] = make_float2(sc[i0], sc[i1]);
        g_meta[p] = i0 | (i1 << 8) | (lvl << 16);
    }
    int cnt = (qt == 0 && p < P) ? (1 << lvl) : 0;
    int ws = __reduce_add_sync(0xffffffffu, cnt);
    if (lane == 0) wsum[t >> 5] = ws;
    __syncthreads();
    if (t == 0) {
        int sum = 0;
#pragma unroll
        for (int i = 0; i < 8; i++) sum += wsum[i];
        g_bsum[blockIdx.x] = sum;
    }
}

// ---------------------------------------------------------------------------
// Kernel 2: per-patch starts. Block offset = redundant reduce of preceding
// 64-patch sums (4*bid entries from L2), then intra-block shfl scan.
// ---------------------------------------------------------------------------
__global__ void starts_kernel(int P) {
    __shared__ int ws[8];
    __shared__ int bofs;
    int t = threadIdx.x, lane = t & 31, wp = t >> 5;
    int p = blockIdx.x * 256 + t;

    int lim = blockIdx.x * 4;
    int bo = (t < lim) ? g_bsum[t] : 0;
    for (int i = t + 256; i < lim; i += 256) bo += g_bsum[i];
    bo = __reduce_add_sync(0xffffffffu, bo);
    if (lane == 0) ws[wp] = bo;
    __syncthreads();
    if (t == 0) {
        int s = 0;
#pragma unroll
        for (int i = 0; i < 8; i++) s += ws[i];
        bofs = s;
    }
    __syncthreads();

    int cnt = (p < P) ? (1 << ((g_meta[p] >> 16) & 3)) : 0;
    int inc = cnt;
#pragma unroll
    for (int o = 1; o < 32; o <<= 1) {
        int u = __shfl_up_sync(0xffffffffu, inc, o);
        if (lane >= o) inc += u;
    }
    __syncthreads();
    if (lane == 31) ws[wp] = inc;
    __syncthreads();
    if (wp == 0) {
        int s = (lane < 8) ? ws[lane] : 0;
#pragma unroll
        for (int o = 1; o < 8; o <<= 1) {
            int u = __shfl_up_sync(0xffffffffu, s, o);
            if (lane >= o) s += u;
        }
        if (lane < 8) ws[lane] = s;
    }
    __syncthreads();
    int off = wp ? ws[wp - 1] : 0;
    if (p < P) g_start[p] = bofs + off + inc - cnt;
}

// ---------------------------------------------------------------------------
// Kernel 3: writer, ONE WARP per patch. new_x/new_mask always via STG.128.
// x_final: if T is even (8B-aligned section base) use float2 stores where
// lane L owns value-pair (L&15) and wave k stores rows {2k, 2k+1}; else the
// proven coalesced-scalar switch. Output layout (floats):
//   [0,32T) new_x   [32T,64T) new_mask  [64T,65T) new_size
//   [65T,67T) weights  [67T,69T) expert_idx  [69T,165T) x_final [T,3,32]
// ---------------------------------------------------------------------------
template <bool EVEN>
__global__ void write_kernel(const float* __restrict__ x,
                             const float* __restrict__ mask,
                             float* __restrict__ out, int P, unsigned T) {
    unsigned w = (blockIdx.x * blockDim.x + threadIdx.x) >> 5;
    unsigned lane = threadIdx.x & 31;
    if (w >= (unsigned)P) return;

    int meta = g_meta[w];
    unsigned start = (unsigned)g_start[w];
    int i0 = meta & 255, i1 = (meta >> 8) & 255, lvl = (meta >> 16) & 3;
    int cnt = 1 << lvl, sz = 32 >> lvl;

    // ---- new_x / new_mask: always 16B-aligned vector stores ----
    {
        const float4* xp = (const float4*)x + (unsigned)w * 8u;
        const float4* mp = (const float4*)mask + (unsigned)w * 8u;
        int c = lane >> 3, q = lane & 7;
        bool qv = (q * 4) < sz;
        int gi = qv ? ((c * sz) >> 2) + q : 0;
        float4 gx = xp[gi];
        float4 gm = mp[gi];
        if (!qv) { gx = make_float4(0.f,0.f,0.f,0.f);
                   gm = make_float4(0.f,0.f,0.f,0.f); }
        if (c < cnt) {
            float4* out4 = (float4*)out;
            unsigned idx4 = (start + c) * 8u + q;
            out4[idx4] = gx;
            out4[T * 8u + idx4] = gm;
        }
    }

    // ---- small fields ----
    float* ps = out + T * 64u + start;
    float* pw = out + T * 65u + start * 2u + lane;
    float* pe = out + T * 67u + start * 2u + lane;
    if (lane < (unsigned)cnt) ps[lane] = (float)sz;
    if (lane < (unsigned)(cnt * 2)) {
        float2 wv = g_w2[w];
        pw[0] = (lane & 1) ? wv.y : wv.x;
        pe[0] = (float)((lane & 1) ? i1 : i0);
    }

    // ---- x_final ----
    if (EVEN) {
        unsigned q16 = lane & 15u, h = lane >> 4;
        float2 xw = ((const float2*)x)[w * 16u + q16];
        float2 mw = ((const float2*)mask)[w * 16u + q16];
        float2 pm2 = make_float2(xw.x * mw.x, xw.y * mw.y);
        const float2 z2 = make_float2(0.f, 0.f);
        int rows = 3 * cnt;
        int j0 = (int)(q16 * 2u);
        unsigned b2 = (T >> 1) * 69u + start * 48u + q16;   // float2 units
#pragma unroll
        for (int rb = 0; rb < 12; rb += 2) {
            if (rb >= rows) break;
            int row = rb + (int)h;
            int c = (row * 11) >> 5;       // row/3 for row<12
            int l = row - 3 * c;
            bool on = false;
            if (l == lvl) {
                int lo = c * sz; on = (j0 >= lo) & (j0 < lo + sz);
            } else if (lvl >= 1 && l == lvl - 1) {
                int lo = (c >> 1) * (sz * 2);
                on = (j0 >= lo) & (j0 < lo + sz * 2);
            }
            float2 v = on ? pm2 : z2;
            if (row < rows) ((float2*)out)[b2 + (unsigned)row * 16u] = v;
        }
    } else {
        float xv = x[w * 32u + lane];
        float mv = mask[w * 32u + lane];
        float pm = xv * mv;
        float* pf = out + T * 69u + start * 96u + lane;
        switch (lvl) {
        case 0:
            pf[0] = pm;  pf[32] = 0.f;  pf[64] = 0.f;
            break;
        case 1: {
            bool lo = lane < 16, hi = !lo;
            pf[0]  = pm;  pf[32]  = lo ? pm : 0.f;  pf[64]  = 0.f;
            pf[96] = pm;  pf[128] = hi ? pm : 0.f;  pf[160] = 0.f;
            break;
        }
        default: {
            bool h0 = lane < 16, h1 = !h0;
            bool o0 = lane < 8, o1 = (lane >= 8) & h0;
            bool o2 = (lane >= 16) & (lane < 24), o3 = lane >= 24;
            pf[0]   = 0.f;  pf[32]  = h0 ? pm : 0.f;  pf[64]  = o0 ? pm : 0.f;
            pf[96]  = 0.f;  pf[128] = h0 ? pm : 0.f;  pf[160] = o1 ? pm : 0.f;
            pf[192] = 0.f;  pf[224] = h1 ? pm : 0.f;  pf[256] = o2 ? pm : 0.f;
            pf[288] = 0.f;  pf[320] = h1 ? pm : 0.f;  pf[352] = o3 ? pm : 0.f;
            break;
        }
        }
    }
}

// ---------------------------------------------------------------------------
extern "C" void kernel_launch(void* const* d_in, const int* in_sizes, int n_in,
                              void* d_out, int out_size) {
    const float* x    = (const float*)d_in[0];
    const float* mask = (const float*)d_in[1];
    const float* Wg   = (const float*)d_in[2];
    float* out = (float*)d_out;

    int n = in_sizes[0];
    int P = n / PATCH;                 // 65536
    unsigned T = (unsigned)(out_size / 165);

    gate_kernel<<<(P + 63) / 64, 256>>>((const float4*)x, (const float4*)Wg, P);
    starts_kernel<<<(P + 255) / 256, 256>>>(P);
    int wb = (P * 32 + 255) / 256;
    if ((T & 1u) == 0)
        write_kernel<true><<<wb, 256>>>(x, mask, out, P, T);
    else
        write_kernel<false><<<wb, 256>>>(x, mask, out, P, T);
}